// round 3
// baseline (speedup 1.0000x reference)
#include <cuda_runtime.h>
#include <math.h>

// ---------------------------------------------------------------------------
// Problem constants (shapes are fixed by the dataset; B and T are re-derived
// from in_sizes/out_size at launch for safety).
//   x:[B,256]  W1:[512,273] b1:[512]  W2:[512,512] b2  W3:[512,512] b3
//   Wih:[2048,512] Whh:[2048,512] bih:[2048] bhh:[2048]  sentence_len (int)
//   out:[B,T,512] fp32
// ---------------------------------------------------------------------------

#define MAXB 8192

// Scratch (static device globals -- allocation-free per harness rules)
__device__ __align__(256) float g_W1x[512 * 256];      // packed W1[:,17:273]
__device__ __align__(256) float g_b1eff[512];          // b1 + W1[:, 20-len]
__device__ __align__(256) float g_Wcomb[2048 * 512];   // Wih + Whh
__device__ __align__(256) float g_biasc[2048];         // bih + bhh
__device__ __align__(256) float g_h1[MAXB * 512];
__device__ __align__(256) float g_h2[MAXB * 512];
__device__ __align__(256) float g_h[MAXB * 512];       // x0, then h_t
__device__ __align__(256) float g_c[MAXB * 512];
__device__ __align__(256) float g_gates[MAXB * 2048];

// ---------------------------------------------------------------------------
// prep: Wcomb = Wih+Whh, biasc = bih+bhh, pack W1 noise columns, fold the
// one-hot column into b1.
// ---------------------------------------------------------------------------
__global__ void prep_kernel(const float* __restrict__ W1, const float* __restrict__ b1,
                            const float* __restrict__ Wih, const float* __restrict__ Whh,
                            const float* __restrict__ bih, const float* __restrict__ bhh,
                            const int* __restrict__ slen)
{
    int i = blockIdx.x * blockDim.x + threadIdx.x;
    if (i < 2048 * 512) g_Wcomb[i] = Wih[i] + Whh[i];
    if (i < 2048)       g_biasc[i] = bih[i] + bhh[i];
    if (i < 512 * 256) {
        int n = i >> 8, k = i & 255;
        g_W1x[i] = W1[n * 273 + 17 + k];
    }
    if (i < 512) {
        int hot = 20 - *slen;            // MAX_LEN - sentence_len
        g_b1eff[i] = b1[i] + W1[i * 273 + hot];
    }
}

// ---------------------------------------------------------------------------
// tf32 tensor-core GEMM:  C[M,N] = act( A[M,K] * W[N,K]^T + bias[N] )
// Block tile 128x128, BK=16, 8 warps (2x4), warp tile 64x32, mma m16n8k8.
// M, N must be multiples of 128 (true here: M=8192, N in {512,2048}).
// ACT: 0 = none, 1 = relu, 2 = sigmoid.
// ---------------------------------------------------------------------------
__device__ __forceinline__ unsigned f2tf(float x) {
    unsigned u;
    asm("cvt.rna.tf32.f32 %0, %1;" : "=r"(u) : "f"(x));
    return u;
}

__device__ __forceinline__ float sigmf_(float x) { return 1.f / (1.f + expf(-x)); }

template <int ACT>
__global__ __launch_bounds__(256, 2)
void gemm_tf32(const float* __restrict__ A, int lda,
               const float* __restrict__ B, int ldb,
               const float* __restrict__ bias,
               float* __restrict__ C, int ldc, int K)
{
    // stride 20 floats: (20*r + q) mod 32 covers all 32 banks for r=0..7, q=0..3
    __shared__ __align__(16) unsigned As[128][20];
    __shared__ __align__(16) unsigned Bs[128][20];

    const int tid  = threadIdx.x;
    const int lane = tid & 31;
    const int warp = tid >> 5;
    const int wm = (warp >> 2) * 64;   // warp row offset (2 warps in M)
    const int wn = (warp & 3) * 32;    // warp col offset (4 warps in N)
    const int r = lane >> 2;           // mma groupID
    const int q = lane & 3;            // mma threadID_in_group

    const float* Ab = A + (size_t)blockIdx.y * 128 * lda;
    const float* Bb = B + (size_t)blockIdx.x * 128 * ldb;

    const int lr = tid >> 2;           // loader row 0..63 (and +64)
    const int lc = (tid & 3) << 2;     // loader col {0,4,8,12}

    float acc[4][4][4];
    #pragma unroll
    for (int i = 0; i < 4; i++)
        #pragma unroll
        for (int j = 0; j < 4; j++)
            #pragma unroll
            for (int k = 0; k < 4; k++) acc[i][j][k] = 0.f;

    for (int k0 = 0; k0 < K; k0 += 16) {
        float4 av0 = *(const float4*)(Ab + (size_t)lr        * lda + k0 + lc);
        float4 av1 = *(const float4*)(Ab + (size_t)(lr + 64) * lda + k0 + lc);
        float4 bv0 = *(const float4*)(Bb + (size_t)lr        * ldb + k0 + lc);
        float4 bv1 = *(const float4*)(Bb + (size_t)(lr + 64) * ldb + k0 + lc);
        __syncthreads();
        *(uint4*)&As[lr][lc]      = make_uint4(f2tf(av0.x), f2tf(av0.y), f2tf(av0.z), f2tf(av0.w));
        *(uint4*)&As[lr + 64][lc] = make_uint4(f2tf(av1.x), f2tf(av1.y), f2tf(av1.z), f2tf(av1.w));
        *(uint4*)&Bs[lr][lc]      = make_uint4(f2tf(bv0.x), f2tf(bv0.y), f2tf(bv0.z), f2tf(bv0.w));
        *(uint4*)&Bs[lr + 64][lc] = make_uint4(f2tf(bv1.x), f2tf(bv1.y), f2tf(bv1.z), f2tf(bv1.w));
        __syncthreads();

        #pragma unroll
        for (int kk = 0; kk < 16; kk += 8) {
            unsigned af[4][4], bf[4][2];
            #pragma unroll
            for (int mi = 0; mi < 4; mi++) {
                af[mi][0] = As[wm + mi * 16 + r    ][kk + q    ];
                af[mi][1] = As[wm + mi * 16 + 8 + r][kk + q    ];
                af[mi][2] = As[wm + mi * 16 + r    ][kk + q + 4];
                af[mi][3] = As[wm + mi * 16 + 8 + r][kk + q + 4];
            }
            #pragma unroll
            for (int ni = 0; ni < 4; ni++) {
                bf[ni][0] = Bs[wn + ni * 8 + r][kk + q    ];
                bf[ni][1] = Bs[wn + ni * 8 + r][kk + q + 4];
            }
            #pragma unroll
            for (int mi = 0; mi < 4; mi++)
                #pragma unroll
                for (int ni = 0; ni < 4; ni++)
                    asm volatile(
                        "mma.sync.aligned.m16n8k8.row.col.f32.tf32.tf32.f32 "
                        "{%0,%1,%2,%3}, {%4,%5,%6,%7}, {%8,%9}, {%0,%1,%2,%3};\n"
                        : "+f"(acc[mi][ni][0]), "+f"(acc[mi][ni][1]),
                          "+f"(acc[mi][ni][2]), "+f"(acc[mi][ni][3])
                        : "r"(af[mi][0]), "r"(af[mi][1]), "r"(af[mi][2]), "r"(af[mi][3]),
                          "r"(bf[ni][0]), "r"(bf[ni][1]));
        }
    }

    // epilogue: bias + activation, float2 stores (c0/c1 are adjacent columns)
    #pragma unroll
    for (int mi = 0; mi < 4; mi++) {
        int m0 = blockIdx.y * 128 + wm + mi * 16 + r;
        #pragma unroll
        for (int ni = 0; ni < 4; ni++) {
            int n = blockIdx.x * 128 + wn + ni * 8 + q * 2;
            float b0v = bias[n], b1v = bias[n + 1];
            float v00 = acc[mi][ni][0] + b0v, v01 = acc[mi][ni][1] + b1v;
            float v10 = acc[mi][ni][2] + b0v, v11 = acc[mi][ni][3] + b1v;
            if (ACT == 1) {
                v00 = fmaxf(v00, 0.f); v01 = fmaxf(v01, 0.f);
                v10 = fmaxf(v10, 0.f); v11 = fmaxf(v11, 0.f);
            } else if (ACT == 2) {
                v00 = sigmf_(v00); v01 = sigmf_(v01);
                v10 = sigmf_(v10); v11 = sigmf_(v11);
            }
            *(float2*)(C + (size_t)m0 * ldc + n)       = make_float2(v00, v01);
            *(float2*)(C + (size_t)(m0 + 8) * ldc + n) = make_float2(v10, v11);
        }
    }
}

// ---------------------------------------------------------------------------
// LSTM pointwise: reads g_gates[B,2048] (torch order i,f,g,o), updates g_c,
// g_h, writes out[b,t,:].
// ---------------------------------------------------------------------------
template <bool FIRST>
__global__ void lstm_pw(float* __restrict__ out, int t, int B, int T)
{
    int idx = blockIdx.x * blockDim.x + threadIdx.x;
    if (idx >= B * 512) return;
    int b = idx >> 9, j = idx & 511;
    const float* g = g_gates + (size_t)b * 2048;
    float gi = sigmf_(g[j]);
    float gf = sigmf_(g[j + 512]);
    float gg = tanhf(g[j + 1024]);
    float go = sigmf_(g[j + 1536]);
    float cn = FIRST ? (gi * gg) : fmaf(gf, g_c[idx], gi * gg);
    g_c[idx] = cn;
    float hn = go * tanhf(cn);
    g_h[idx] = hn;
    out[((size_t)b * T + t) * 512 + j] = hn;
}

// ---------------------------------------------------------------------------
// launch
// ---------------------------------------------------------------------------
extern "C" void kernel_launch(void* const* d_in, const int* in_sizes, int n_in,
                              void* d_out, int out_size)
{
    const float* x   = (const float*)d_in[0];
    const float* W1  = (const float*)d_in[1];
    const float* b1  = (const float*)d_in[2];
    const float* W2  = (const float*)d_in[3];
    const float* b2  = (const float*)d_in[4];
    const float* W3  = (const float*)d_in[5];
    const float* b3  = (const float*)d_in[6];
    const float* Wih = (const float*)d_in[7];
    const float* Whh = (const float*)d_in[8];
    const float* bih = (const float*)d_in[9];
    const float* bhh = (const float*)d_in[10];
    const int*   sl  = (const int*)d_in[11];
    float* out = (float*)d_out;

    const int B = in_sizes[0] / 256;          // 8192
    const int T = out_size / (B * 512);       // 16

    float *W1x_, *b1eff_, *Wcomb_, *biasc_, *h1_, *h2_, *h_, *gates_;
    cudaGetSymbolAddress((void**)&W1x_,   g_W1x);
    cudaGetSymbolAddress((void**)&b1eff_, g_b1eff);
    cudaGetSymbolAddress((void**)&Wcomb_, g_Wcomb);
    cudaGetSymbolAddress((void**)&biasc_, g_biasc);
    cudaGetSymbolAddress((void**)&h1_,    g_h1);
    cudaGetSymbolAddress((void**)&h2_,    g_h2);
    cudaGetSymbolAddress((void**)&h_,     g_h);
    cudaGetSymbolAddress((void**)&gates_, g_gates);

    dim3 blk(256);
    dim3 gMLP(512 / 128, B / 128);    // (4, 64)
    dim3 gGate(2048 / 128, B / 128);  // (16, 64)
    int pw_blocks = (B * 512 + 255) / 256;

    prep_kernel<<<(2048 * 512 + 255) / 256, 256>>>(W1, b1, Wih, Whh, bih, bhh, sl);

    // MLP: h1 = relu(x W1x^T + b1eff); h2 = relu(h1 W2^T + b2); x0 = sigmoid(h2 W3^T + b3)
    gemm_tf32<1><<<gMLP, blk>>>(x,   256, W1x_, 256, b1eff_, h1_, 512, 256);
    gemm_tf32<1><<<gMLP, blk>>>(h1_, 512, W2,   512, b2,     h2_, 512, 512);
    gemm_tf32<2><<<gMLP, blk>>>(h2_, 512, W3,   512, b3,     h_,  512, 512);  // x0 -> g_h

    for (int t = 0; t < T; ++t) {
        const float* Wg = (t == 0) ? Wih : Wcomb_;   // step 0: h=0 so only Wih term
        gemm_tf32<0><<<gGate, blk>>>(h_, 512, Wg, 512, biasc_, gates_, 2048, 512);
        if (t == 0) lstm_pw<true><<<pw_blocks, 256>>>(out, t, B, T);
        else        lstm_pw<false><<<pw_blocks, 256>>>(out, t, B, T);
    }
}

// round 4
// speedup vs baseline: 1.3426x; 1.3426x over previous
#include <cuda_runtime.h>
#include <math.h>

// ---------------------------------------------------------------------------
//   x:[B,256]  W1:[512,273] b1:[512]  W2:[512,512] b2  W3:[512,512] b3
//   Wih:[2048,512] Whh:[2048,512] bih:[2048] bhh:[2048]  sentence_len (int)
//   out:[B,T,512] fp32
//
// Strategy: tf32 mma.sync GEMMs with k-permuted global operand layout so the
// mainloop does cp.async (raw, pre-rounded tf32 bits) + LDS.128 fragment
// loads + HMMA only. LSTM recurrence algebra: inp==h after step 0, so use
// Wcomb = Wih + Whh (halves LSTM FLOPs).
// ---------------------------------------------------------------------------

#define MAXB 8192

// Scratch (static device globals -- allocation-free per harness rules)
__device__ __align__(256) float g_W1x[512 * 256];      // permuted+rounded W1[:,17:273]
__device__ __align__(256) float g_b1eff[512];          // b1 + W1[:, 20-len]
__device__ __align__(256) float g_Wcomb[2048 * 512];   // perm+round (Wih+Whh)
__device__ __align__(256) float g_Wihp[2048 * 512];    // perm+round Wih (t=0)
__device__ __align__(256) float g_W2p[512 * 512];
__device__ __align__(256) float g_W3p[512 * 512];
__device__ __align__(256) float g_biasc[2048];         // bih + bhh
__device__ __align__(256) float g_xp[MAXB * 256];      // perm+round x
__device__ __align__(256) float g_h1[MAXB * 512];
__device__ __align__(256) float g_h2[MAXB * 512];
__device__ __align__(256) float g_h[MAXB * 512];       // perm+round x0 / h_t
__device__ __align__(256) float g_c[MAXB * 512];
__device__ __align__(256) float g_gates[MAXB * 2048];

// ---------------------------------------------------------------------------
// helpers
// ---------------------------------------------------------------------------
__device__ __forceinline__ unsigned f2tf(float x) {
    unsigned u;
    asm("cvt.rna.tf32.f32 %0, %1;" : "=r"(u) : "f"(x));
    return u;
}
__device__ __forceinline__ float tf32f(float x) { return __uint_as_float(f2tf(x)); }

// involutive k-permutation within 16-blocks: swaps the two 2-bit fields.
// Position p holds original k = perm16(p); also the store-side map.
__device__ __forceinline__ int perm16(int p) {
    return (p & ~15) | ((p & 3) << 2) | ((p >> 2) & 3);
}

__device__ __forceinline__ float fsig(float x)  { return 1.f / (1.f + __expf(-x)); }
__device__ __forceinline__ float ftanh(float x) { return 2.f / (1.f + __expf(-2.f * x)) - 1.f; }
__device__ __forceinline__ float sigacc(float x) { return 1.f / (1.f + expf(-x)); }

__device__ __forceinline__ void cpasync16(void* dst, const void* src) {
    unsigned d = (unsigned)__cvta_generic_to_shared(dst);
    asm volatile("cp.async.cg.shared.global [%0], [%1], 16;\n" :: "r"(d), "l"(src));
}

__device__ __forceinline__ void mma8(float* c,
                                     unsigned a0, unsigned a1, unsigned a2, unsigned a3,
                                     unsigned b0, unsigned b1) {
    asm volatile(
        "mma.sync.aligned.m16n8k8.row.col.f32.tf32.tf32.f32 "
        "{%0,%1,%2,%3}, {%4,%5,%6,%7}, {%8,%9}, {%0,%1,%2,%3};\n"
        : "+f"(c[0]), "+f"(c[1]), "+f"(c[2]), "+f"(c[3])
        : "r"(a0), "r"(a1), "r"(a2), "r"(a3), "r"(b0), "r"(b1));
}

// ---------------------------------------------------------------------------
// prep: build permuted + tf32-rounded weight/activation copies, fused biases.
// Launched with >= 2M threads (grid-stride not needed; one task per i).
// ---------------------------------------------------------------------------
__global__ void prep_kernel(const float* __restrict__ x,
                            const float* __restrict__ W1, const float* __restrict__ b1,
                            const float* __restrict__ W2, const float* __restrict__ W3,
                            const float* __restrict__ Wih, const float* __restrict__ Whh,
                            const float* __restrict__ bih, const float* __restrict__ bhh,
                            const int* __restrict__ slen, int B)
{
    int i = blockIdx.x * blockDim.x + threadIdx.x;

    if (i < 2048 * 512) {                       // LSTM weights
        int n = i >> 9, p = i & 511;
        int k = perm16(p);
        float wv = Wih[n * 512 + k];
        float wh = Whh[n * 512 + k];
        g_Wihp[i]  = tf32f(wv);
        g_Wcomb[i] = tf32f(wv + wh);
    }
    if (i < 512 * 512) {                        // W2, W3
        int n = i >> 9, p = i & 511;
        int k = perm16(p);
        g_W2p[i] = tf32f(W2[n * 512 + k]);
        g_W3p[i] = tf32f(W3[n * 512 + k]);
    }
    if (i < 512 * 256) {                        // W1 noise columns
        int n = i >> 8, p = i & 255;
        g_W1x[i] = tf32f(W1[n * 273 + 17 + perm16(p)]);
    }
    if (i < B * 256) {                          // x permuted+rounded
        int b = i >> 8, p = i & 255;
        g_xp[i] = tf32f(x[b * 256 + perm16(p)]);
    }
    if (i < 2048) g_biasc[i] = bih[i] + bhh[i];
    if (i < 512) {
        int hot = 20 - *slen;
        g_b1eff[i] = b1[i] + W1[i * 273 + hot];
    }
}

// ---------------------------------------------------------------------------
// tf32 tensor-core GEMM: C[M,N] = act( A[M,K] * W[N,K]^T + bias[N] )
// A, W are stored k-PERMUTED and tf32-pre-rounded. Block 128x128, BK=16,
// 3-stage cp.async pipeline, 8 warps (2x4), warp tile 64x32, mma m16n8k8.
// ACT: 0=none, 1=relu, 2=sigmoid. PERM: epilogue stores k-permuted + rounded
// (when C feeds a subsequent GEMM as A).
// ---------------------------------------------------------------------------
template <int ACT, int PERM>
__global__ __launch_bounds__(256, 2)
void gemm_tc(const float* __restrict__ A, int lda,
             const float* __restrict__ Bm, int ldb,
             const float* __restrict__ bias,
             float* __restrict__ C, int ldc, int K)
{
    // [stage][row*4 + swizzled_chunk]; swizzle: chunk ^ ((row>>1)&3).
    // 3*512*16B*2 = 48KB static smem exactly.
    __shared__ float4 As[3][512];
    __shared__ float4 Bs[3][512];

    const int tid  = threadIdx.x;
    const int lane = tid & 31;
    const int warp = tid >> 5;
    const int wm = (warp >> 2) * 64;
    const int wn = (warp & 3) * 32;
    const int r = lane >> 2;
    const int q = lane & 3;

    const float* Ab = A  + (size_t)blockIdx.y * 128 * lda;
    const float* Bb = Bm + (size_t)blockIdx.x * 128 * ldb;

    const int lr = tid >> 2;          // 0..63 (and +64)
    const int lc = tid & 3;           // chunk 0..3
    const int KT = K >> 4;

    float acc[4][4][4];
    #pragma unroll
    for (int i = 0; i < 4; i++)
        #pragma unroll
        for (int j = 0; j < 4; j++)
            #pragma unroll
            for (int k = 0; k < 4; k++) acc[i][j][k] = 0.f;

    auto ld_stage = [&](int s, int kt) {
        const int k0 = kt << 4;
        int row = lr;
        cpasync16(&As[s][row * 4 + (lc ^ ((row >> 1) & 3))],
                  Ab + (size_t)row * lda + k0 + 4 * lc);
        cpasync16(&Bs[s][row * 4 + (lc ^ ((row >> 1) & 3))],
                  Bb + (size_t)row * ldb + k0 + 4 * lc);
        row = lr + 64;
        cpasync16(&As[s][row * 4 + (lc ^ ((row >> 1) & 3))],
                  Ab + (size_t)row * lda + k0 + 4 * lc);
        cpasync16(&Bs[s][row * 4 + (lc ^ ((row >> 1) & 3))],
                  Bb + (size_t)row * ldb + k0 + 4 * lc);
        asm volatile("cp.async.commit_group;\n" ::);
    };

    ld_stage(0, 0);
    ld_stage(1, 1);

    for (int kt = 0; kt < KT; kt++) {
        const int s = kt % 3;
        asm volatile("cp.async.wait_group 1;\n" ::);
        __syncthreads();

        const int ktn = kt + 2;
        if (ktn < KT) ld_stage(ktn % 3, ktn);

        // Fragment loads: position 4q..4q+3 holds k = q, q+4, q+8, q+12.
        uint4 af[4][2], bf[4];
        #pragma unroll
        for (int mi = 0; mi < 4; mi++) {
            int r0 = wm + mi * 16 + r;
            af[mi][0] = *(const uint4*)&As[s][r0 * 4 + (q ^ ((r0 >> 1) & 3))];
            int r1 = r0 + 8;
            af[mi][1] = *(const uint4*)&As[s][r1 * 4 + (q ^ ((r1 >> 1) & 3))];
        }
        #pragma unroll
        for (int ni = 0; ni < 4; ni++) {
            int rb = wn + ni * 8 + r;
            bf[ni] = *(const uint4*)&Bs[s][rb * 4 + (q ^ ((rb >> 1) & 3))];
        }

        // kk = 0..7  (k = q, q+4)
        #pragma unroll
        for (int mi = 0; mi < 4; mi++)
            #pragma unroll
            for (int ni = 0; ni < 4; ni++)
                mma8(acc[mi][ni],
                     af[mi][0].x, af[mi][1].x, af[mi][0].y, af[mi][1].y,
                     bf[ni].x, bf[ni].y);
        // kk = 8..15 (k = q+8, q+12)
        #pragma unroll
        for (int mi = 0; mi < 4; mi++)
            #pragma unroll
            for (int ni = 0; ni < 4; ni++)
                mma8(acc[mi][ni],
                     af[mi][0].z, af[mi][1].z, af[mi][0].w, af[mi][1].w,
                     bf[ni].z, bf[ni].w);
    }

    // epilogue: bias + activation
    #pragma unroll
    for (int mi = 0; mi < 4; mi++) {
        int m0 = blockIdx.y * 128 + wm + mi * 16 + r;
        #pragma unroll
        for (int ni = 0; ni < 4; ni++) {
            int n = blockIdx.x * 128 + wn + ni * 8 + 2 * q;
            float b0v = bias[n], b1v = bias[n + 1];
            float v00 = acc[mi][ni][0] + b0v, v01 = acc[mi][ni][1] + b1v;
            float v10 = acc[mi][ni][2] + b0v, v11 = acc[mi][ni][3] + b1v;
            if (ACT == 1) {
                v00 = fmaxf(v00, 0.f); v01 = fmaxf(v01, 0.f);
                v10 = fmaxf(v10, 0.f); v11 = fmaxf(v11, 0.f);
            } else if (ACT == 2) {
                v00 = sigacc(v00); v01 = sigacc(v01);
                v10 = sigacc(v10); v11 = sigacc(v11);
            }
            if (PERM) {
                // feeds next GEMM as A: store permuted + tf32-rounded
                int p0 = perm16(n), p1 = perm16(n + 1);
                C[(size_t)m0 * ldc + p0]       = tf32f(v00);
                C[(size_t)m0 * ldc + p1]       = tf32f(v01);
                C[(size_t)(m0 + 8) * ldc + p0] = tf32f(v10);
                C[(size_t)(m0 + 8) * ldc + p1] = tf32f(v11);
            } else {
                *(float2*)(C + (size_t)m0 * ldc + n)       = make_float2(v00, v01);
                *(float2*)(C + (size_t)(m0 + 8) * ldc + n) = make_float2(v10, v11);
            }
        }
    }
}

// ---------------------------------------------------------------------------
// LSTM pointwise (4-wide): reads g_gates[B,2048] (i,f,g,o), updates g_c,
// writes out[b,t,:] (full fp32) and g_h (permuted + tf32-rounded GEMM input).
// ---------------------------------------------------------------------------
template <bool FIRST>
__global__ void lstm_pw(float* __restrict__ out, int t, int B, int T)
{
    int idx = blockIdx.x * blockDim.x + threadIdx.x;
    if (idx >= B * 128) return;
    int b = idx >> 7, j4 = (idx & 127) << 2;
    const float* g = g_gates + (size_t)b * 2048;

    float4 gi4 = *(const float4*)(g + j4);
    float4 gf4 = *(const float4*)(g + 512 + j4);
    float4 gg4 = *(const float4*)(g + 1024 + j4);
    float4 go4 = *(const float4*)(g + 1536 + j4);

    float gi[4] = {gi4.x, gi4.y, gi4.z, gi4.w};
    float gf[4] = {gf4.x, gf4.y, gf4.z, gf4.w};
    float gg[4] = {gg4.x, gg4.y, gg4.z, gg4.w};
    float go[4] = {go4.x, go4.y, go4.z, go4.w};

    float co[4] = {0.f, 0.f, 0.f, 0.f};
    if (!FIRST) {
        float4 c4 = *(const float4*)(g_c + (size_t)b * 512 + j4);
        co[0] = c4.x; co[1] = c4.y; co[2] = c4.z; co[3] = c4.w;
    }

    float cn[4], hn[4];
    #pragma unroll
    for (int i = 0; i < 4; i++) {
        float ii = fsig(gi[i]);
        float ff = fsig(gf[i]);
        float g_ = ftanh(gg[i]);
        float oo = fsig(go[i]);
        float c = FIRST ? (ii * g_) : fmaf(ff, co[i], ii * g_);
        cn[i] = c;
        hn[i] = oo * ftanh(c);
    }

    *(float4*)(g_c + (size_t)b * 512 + j4) = make_float4(cn[0], cn[1], cn[2], cn[3]);
    *(float4*)(out + ((size_t)b * T + t) * 512 + j4) = make_float4(hn[0], hn[1], hn[2], hn[3]);

    // permuted + rounded copy for the next gates GEMM (j4 is 4-aligned:
    // perm16(j4+i) = (j4&~15) | (i<<2) | ((j4>>2)&3))
    float* hp = g_h + (size_t)b * 512;
    int pb = (j4 & ~15) | ((j4 >> 2) & 3);
    #pragma unroll
    for (int i = 0; i < 4; i++) hp[pb | (i << 2)] = tf32f(hn[i]);
}

// ---------------------------------------------------------------------------
// launch
// ---------------------------------------------------------------------------
extern "C" void kernel_launch(void* const* d_in, const int* in_sizes, int n_in,
                              void* d_out, int out_size)
{
    const float* x   = (const float*)d_in[0];
    const float* W1  = (const float*)d_in[1];
    const float* b1  = (const float*)d_in[2];
    const float* W2  = (const float*)d_in[3];
    const float* b2  = (const float*)d_in[4];
    const float* W3  = (const float*)d_in[5];
    const float* b3  = (const float*)d_in[6];
    const float* Wih = (const float*)d_in[7];
    const float* Whh = (const float*)d_in[8];
    const float* bih = (const float*)d_in[9];
    const float* bhh = (const float*)d_in[10];
    const int*   sl  = (const int*)d_in[11];
    float* out = (float*)d_out;

    const int B = in_sizes[0] / 256;          // 8192
    const int T = out_size / (B * 512);       // 16

    float *W1x_, *b1eff_, *Wcomb_, *Wihp_, *W2p_, *W3p_, *biasc_, *xp_,
          *h1_, *h2_, *h_, *gates_;
    cudaGetSymbolAddress((void**)&W1x_,   g_W1x);
    cudaGetSymbolAddress((void**)&b1eff_, g_b1eff);
    cudaGetSymbolAddress((void**)&Wcomb_, g_Wcomb);
    cudaGetSymbolAddress((void**)&Wihp_,  g_Wihp);
    cudaGetSymbolAddress((void**)&W2p_,   g_W2p);
    cudaGetSymbolAddress((void**)&W3p_,   g_W3p);
    cudaGetSymbolAddress((void**)&biasc_, g_biasc);
    cudaGetSymbolAddress((void**)&xp_,    g_xp);
    cudaGetSymbolAddress((void**)&h1_,    g_h1);
    cudaGetSymbolAddress((void**)&h2_,    g_h2);
    cudaGetSymbolAddress((void**)&h_,     g_h);
    cudaGetSymbolAddress((void**)&gates_, g_gates);

    dim3 blk(256);
    dim3 gMLP(512 / 128, B / 128);    // (4, 64)
    dim3 gGate(2048 / 128, B / 128);  // (16, 64)
    int pw_blocks = (B * 128 + 255) / 256;
    int prep_threads = B * 256;                  // 2M covers every prep task
    prep_kernel<<<(prep_threads + 255) / 256, 256>>>(x, W1, b1, W2, W3,
                                                     Wih, Whh, bih, bhh, sl, B);

    // MLP (all operands permuted+rounded; outputs permuted+rounded for next A)
    gemm_tc<1, 1><<<gMLP, blk>>>(xp_, 256, W1x_, 256, b1eff_, h1_, 512, 256);
    gemm_tc<1, 1><<<gMLP, blk>>>(h1_, 512, W2p_, 512, b2,     h2_, 512, 512);
    gemm_tc<2, 1><<<gMLP, blk>>>(h2_, 512, W3p_, 512, b3,     h_,  512, 512); // x0

    for (int t = 0; t < T; ++t) {
        const float* Wg = (t == 0) ? Wihp_ : Wcomb_;   // t=0: h_prev=0
        gemm_tc<0, 0><<<gGate, blk>>>(h_, 512, Wg, 512, biasc_, gates_, 2048, 512);
        if (t == 0) lstm_pw<true><<<pw_blocks, 256>>>(out, t, B, T);
        else        lstm_pw<false><<<pw_blocks, 256>>>(out, t, B, T);
    }
}

// round 5
// speedup vs baseline: 1.3557x; 1.0098x over previous
#include <cuda_runtime.h>
#include <math.h>

// ---------------------------------------------------------------------------
//   x:[B,256]  W1:[512,273] b1:[512]  W2:[512,512] b2  W3:[512,512] b3
//   Wih:[2048,512] Whh:[2048,512] bih:[2048] bhh:[2048]  sentence_len (int)
//   out:[B,T,512] fp32
//
// tf32 mma.sync GEMMs, k-permuted pre-rounded operands (pure cp.async +
// LDS.128 + HMMA mainloop). LSTM algebra: inp==h after step 0 -> Wcomb =
// Wih+Whh halves LSTM FLOPs. LSTM cell fused into the gates-GEMM epilogue
// via gate-interleaved weight layout (n' = 4j+gate) + lane^1 shuffle.
// ---------------------------------------------------------------------------

#define MAXB 8192

__device__ __align__(256) float g_W1x[512 * 256];      // perm+round W1[:,17:273]
__device__ __align__(256) float g_b1eff[512];          // b1 + W1[:, 20-len]
__device__ __align__(256) float g_WcombI[2048 * 512];  // gate-interleaved perm+round (Wih+Whh)
__device__ __align__(256) float g_WihI[2048 * 512];    // gate-interleaved perm+round Wih (t=0)
__device__ __align__(256) float g_biascI[2048];        // gate-interleaved bih+bhh
__device__ __align__(256) float g_W2p[512 * 512];
__device__ __align__(256) float g_W3p[512 * 512];
__device__ __align__(256) float g_xp[MAXB * 256];      // perm+round x
__device__ __align__(256) float g_h1[MAXB * 512];
__device__ __align__(256) float g_h2[MAXB * 512];
__device__ __align__(256) float g_hA[MAXB * 512];      // perm+round h ping
__device__ __align__(256) float g_hB[MAXB * 512];      // perm+round h pong
__device__ __align__(256) float g_c[MAXB * 512];

// ---------------------------------------------------------------------------
// helpers
// ---------------------------------------------------------------------------
__device__ __forceinline__ unsigned f2tf(float x) {
    unsigned u;
    asm("cvt.rna.tf32.f32 %0, %1;" : "=r"(u) : "f"(x));
    return u;
}
__device__ __forceinline__ float tf32f(float x) { return __uint_as_float(f2tf(x)); }

// involutive k-permutation within 16-blocks: swap the two 2-bit fields
__device__ __forceinline__ int perm16(int p) {
    return (p & ~15) | ((p & 3) << 2) | ((p >> 2) & 3);
}

__device__ __forceinline__ float fsig(float x)  { return 1.f / (1.f + __expf(-x)); }
__device__ __forceinline__ float ftanh(float x) { return 2.f / (1.f + __expf(-2.f * x)) - 1.f; }
__device__ __forceinline__ float sigacc(float x) { return 1.f / (1.f + expf(-x)); }

__device__ __forceinline__ void cpasync16(void* dst, const void* src) {
    unsigned d = (unsigned)__cvta_generic_to_shared(dst);
    asm volatile("cp.async.cg.shared.global [%0], [%1], 16;\n" :: "r"(d), "l"(src));
}

__device__ __forceinline__ void mma8(float* c,
                                     unsigned a0, unsigned a1, unsigned a2, unsigned a3,
                                     unsigned b0, unsigned b1) {
    asm volatile(
        "mma.sync.aligned.m16n8k8.row.col.f32.tf32.tf32.f32 "
        "{%0,%1,%2,%3}, {%4,%5,%6,%7}, {%8,%9}, {%0,%1,%2,%3};\n"
        : "+f"(c[0]), "+f"(c[1]), "+f"(c[2]), "+f"(c[3])
        : "r"(a0), "r"(a1), "r"(a2), "r"(a3), "r"(b0), "r"(b1));
}

// ---------------------------------------------------------------------------
// prep
// ---------------------------------------------------------------------------
__global__ void prep_kernel(const float* __restrict__ x,
                            const float* __restrict__ W1, const float* __restrict__ b1,
                            const float* __restrict__ W2, const float* __restrict__ W3,
                            const float* __restrict__ Wih, const float* __restrict__ Whh,
                            const float* __restrict__ bih, const float* __restrict__ bhh,
                            const int* __restrict__ slen, int B)
{
    int i = blockIdx.x * blockDim.x + threadIdx.x;

    if (i < 2048 * 512) {                       // LSTM weights: interleave N, permute K
        int np = i >> 9, p = i & 511;
        int gate = np & 3, j = np >> 2;
        int orig = (gate * 512 + j) * 512 + perm16(p);
        float wv = Wih[orig];
        float wh = Whh[orig];
        g_WihI[i]   = tf32f(wv);
        g_WcombI[i] = tf32f(wv + wh);
    }
    if (i < 512 * 512) {                        // W2, W3 (K-permuted)
        int n = i >> 9, p = i & 511;
        int k = perm16(p);
        g_W2p[i] = tf32f(W2[n * 512 + k]);
        g_W3p[i] = tf32f(W3[n * 512 + k]);
    }
    if (i < 512 * 256) {                        // W1 noise columns
        int n = i >> 8, p = i & 255;
        g_W1x[i] = tf32f(W1[n * 273 + 17 + perm16(p)]);
    }
    if (i < B * 256) {                          // x permuted+rounded
        int b = i >> 8, p = i & 255;
        g_xp[i] = tf32f(x[b * 256 + perm16(p)]);
    }
    if (i < 2048) {                             // interleaved fused bias
        int gate = i & 3, j = i >> 2;
        g_biascI[i] = bih[gate * 512 + j] + bhh[gate * 512 + j];
    }
    if (i < 512) {
        int hot = 20 - *slen;
        g_b1eff[i] = b1[i] + W1[i * 273 + hot];
    }
}

// ---------------------------------------------------------------------------
// MLP GEMM: C[M,N] = act( A[M,K] * W[N,K]^T + bias[N] ), operands k-permuted
// and pre-rounded. Block 128x128, BK=16, 3-stage cp.async, 8 warps (2x4),
// warp 64x32, mma m16n8k8. ACT: 1=relu, 2=sigmoid. Stores permuted+rounded
// (output always feeds a next GEMM as A).
// ---------------------------------------------------------------------------
template <int ACT>
__global__ __launch_bounds__(256, 2)
void gemm_mlp(const float* __restrict__ A, int lda,
              const float* __restrict__ Bm, int ldb,
              const float* __restrict__ bias,
              float* __restrict__ C, int ldc, int K)
{
    __shared__ float4 As[3][512];
    __shared__ float4 Bs[3][512];

    const int tid  = threadIdx.x;
    const int lane = tid & 31;
    const int warp = tid >> 5;
    const int wm = (warp >> 2) * 64;
    const int wn = (warp & 3) * 32;
    const int r = lane >> 2;
    const int q = lane & 3;

    const float* Ab = A  + (size_t)blockIdx.y * 128 * lda;
    const float* Bb = Bm + (size_t)blockIdx.x * 128 * ldb;

    const int lr = tid >> 2;
    const int lc = tid & 3;
    const int KT = K >> 4;

    float acc[4][4][4];
    #pragma unroll
    for (int i = 0; i < 4; i++)
        #pragma unroll
        for (int j = 0; j < 4; j++)
            #pragma unroll
            for (int k = 0; k < 4; k++) acc[i][j][k] = 0.f;

    auto ld_stage = [&](int s, int kt) {
        const int k0 = kt << 4;
        int row = lr;
        cpasync16(&As[s][row * 4 + (lc ^ ((row >> 1) & 3))], Ab + (size_t)row * lda + k0 + 4 * lc);
        cpasync16(&Bs[s][row * 4 + (lc ^ ((row >> 1) & 3))], Bb + (size_t)row * ldb + k0 + 4 * lc);
        row = lr + 64;
        cpasync16(&As[s][row * 4 + (lc ^ ((row >> 1) & 3))], Ab + (size_t)row * lda + k0 + 4 * lc);
        cpasync16(&Bs[s][row * 4 + (lc ^ ((row >> 1) & 3))], Bb + (size_t)row * ldb + k0 + 4 * lc);
        asm volatile("cp.async.commit_group;\n" ::);
    };

    ld_stage(0, 0);
    ld_stage(1, 1);

    for (int kt = 0; kt < KT; kt++) {
        const int s = kt % 3;
        if (kt >= KT - 2) asm volatile("cp.async.wait_group 0;\n" ::);
        else              asm volatile("cp.async.wait_group 1;\n" ::);
        __syncthreads();

        const int ktn = kt + 2;
        if (ktn < KT) ld_stage(ktn % 3, ktn);

        uint4 af[4][2], bf[4];
        #pragma unroll
        for (int mi = 0; mi < 4; mi++) {
            int r0 = wm + mi * 16 + r;
            af[mi][0] = *(const uint4*)&As[s][r0 * 4 + (q ^ ((r0 >> 1) & 3))];
            int r1 = r0 + 8;
            af[mi][1] = *(const uint4*)&As[s][r1 * 4 + (q ^ ((r1 >> 1) & 3))];
        }
        #pragma unroll
        for (int ni = 0; ni < 4; ni++) {
            int rb = wn + ni * 8 + r;
            bf[ni] = *(const uint4*)&Bs[s][rb * 4 + (q ^ ((rb >> 1) & 3))];
        }

        #pragma unroll
        for (int mi = 0; mi < 4; mi++)
            #pragma unroll
            for (int ni = 0; ni < 4; ni++)
                mma8(acc[mi][ni], af[mi][0].x, af[mi][1].x, af[mi][0].y, af[mi][1].y,
                     bf[ni].x, bf[ni].y);
        #pragma unroll
        for (int mi = 0; mi < 4; mi++)
            #pragma unroll
            for (int ni = 0; ni < 4; ni++)
                mma8(acc[mi][ni], af[mi][0].z, af[mi][1].z, af[mi][0].w, af[mi][1].w,
                     bf[ni].z, bf[ni].w);
    }

    #pragma unroll
    for (int mi = 0; mi < 4; mi++) {
        int m0 = blockIdx.y * 128 + wm + mi * 16 + r;
        #pragma unroll
        for (int ni = 0; ni < 4; ni++) {
            int n = blockIdx.x * 128 + wn + ni * 8 + 2 * q;
            float b0v = bias[n], b1v = bias[n + 1];
            float v00 = acc[mi][ni][0] + b0v, v01 = acc[mi][ni][1] + b1v;
            float v10 = acc[mi][ni][2] + b0v, v11 = acc[mi][ni][3] + b1v;
            if (ACT == 1) {
                v00 = fmaxf(v00, 0.f); v01 = fmaxf(v01, 0.f);
                v10 = fmaxf(v10, 0.f); v11 = fmaxf(v11, 0.f);
            } else {
                v00 = sigacc(v00); v01 = sigacc(v01);
                v10 = sigacc(v10); v11 = sigacc(v11);
            }
            int p0 = perm16(n), p1 = perm16(n + 1);
            C[(size_t)m0 * ldc + p0]       = tf32f(v00);
            C[(size_t)m0 * ldc + p1]       = tf32f(v01);
            C[(size_t)(m0 + 8) * ldc + p0] = tf32f(v10);
            C[(size_t)(m0 + 8) * ldc + p1] = tf32f(v11);
        }
    }
}

// ---------------------------------------------------------------------------
// Fused gates-GEMM + LSTM cell.
//   gates[B, 2048 interleaved] = hin @ WgI^T + biasI   (mainloop as above)
//   epilogue: lane^1 shuffle assembles (i,f,g,o) per (m,j), computes cell,
//   stages c/h tiles in smem, coalesced stores of c, out[b,t,:], and the
//   permuted+rounded h for the next step (double-buffered).
// ---------------------------------------------------------------------------
template <int FIRST>
__global__ __launch_bounds__(256, 2)
void gemm_lstm(const float* __restrict__ A,      // hin [B,512] perm+round
               const float* __restrict__ Bm,     // WgI [2048,512]
               const float* __restrict__ bias,   // biascI [2048]
               float* __restrict__ cmem,         // g_c [B,512]
               float* __restrict__ outp,         // out [B,T,512]
               float* __restrict__ hout,         // next h [B,512] perm+round
               int t, int T)
{
    __shared__ float4 SM4[3072];                 // 48KB: pipeline, then tiles
    float4* As = SM4;
    float4* Bs = SM4 + 1536;

    const int tid  = threadIdx.x;
    const int lane = tid & 31;
    const int warp = tid >> 5;
    const int wm = (warp >> 2) * 64;
    const int wn = (warp & 3) * 32;
    const int r = lane >> 2;
    const int q = lane & 3;

    const float* Ab = A  + (size_t)blockIdx.y * 128 * 512;
    const float* Bb = Bm + (size_t)blockIdx.x * 128 * 512;

    const int lr = tid >> 2;
    const int lc = tid & 3;
    const int KT = 32;                           // K = 512

    float acc[4][4][4];
    #pragma unroll
    for (int i = 0; i < 4; i++)
        #pragma unroll
        for (int j = 0; j < 4; j++)
            #pragma unroll
            for (int k = 0; k < 4; k++) acc[i][j][k] = 0.f;

    auto ld_stage = [&](int s, int kt) {
        const int k0 = kt << 4;
        int row = lr;
        cpasync16(&As[s * 512 + row * 4 + (lc ^ ((row >> 1) & 3))], Ab + (size_t)row * 512 + k0 + 4 * lc);
        cpasync16(&Bs[s * 512 + row * 4 + (lc ^ ((row >> 1) & 3))], Bb + (size_t)row * 512 + k0 + 4 * lc);
        row = lr + 64;
        cpasync16(&As[s * 512 + row * 4 + (lc ^ ((row >> 1) & 3))], Ab + (size_t)row * 512 + k0 + 4 * lc);
        cpasync16(&Bs[s * 512 + row * 4 + (lc ^ ((row >> 1) & 3))], Bb + (size_t)row * 512 + k0 + 4 * lc);
        asm volatile("cp.async.commit_group;\n" ::);
    };

    ld_stage(0, 0);
    ld_stage(1, 1);

    for (int kt = 0; kt < KT; kt++) {
        const int s = kt % 3;
        if (kt >= KT - 2) asm volatile("cp.async.wait_group 0;\n" ::);
        else              asm volatile("cp.async.wait_group 1;\n" ::);
        __syncthreads();

        const int ktn = kt + 2;
        if (ktn < KT) ld_stage(ktn % 3, ktn);

        uint4 af[4][2], bf[4];
        #pragma unroll
        for (int mi = 0; mi < 4; mi++) {
            int r0 = wm + mi * 16 + r;
            af[mi][0] = *(const uint4*)&As[s * 512 + r0 * 4 + (q ^ ((r0 >> 1) & 3))];
            int r1 = r0 + 8;
            af[mi][1] = *(const uint4*)&As[s * 512 + r1 * 4 + (q ^ ((r1 >> 1) & 3))];
        }
        #pragma unroll
        for (int ni = 0; ni < 4; ni++) {
            int rb = wn + ni * 8 + r;
            bf[ni] = *(const uint4*)&Bs[s * 512 + rb * 4 + (q ^ ((rb >> 1) & 3))];
        }

        #pragma unroll
        for (int mi = 0; mi < 4; mi++)
            #pragma unroll
            for (int ni = 0; ni < 4; ni++)
                mma8(acc[mi][ni], af[mi][0].x, af[mi][1].x, af[mi][0].y, af[mi][1].y,
                     bf[ni].x, bf[ni].y);
        #pragma unroll
        for (int mi = 0; mi < 4; mi++)
            #pragma unroll
            for (int ni = 0; ni < 4; ni++)
                mma8(acc[mi][ni], af[mi][0].z, af[mi][1].z, af[mi][0].w, af[mi][1].w,
                     bf[ni].z, bf[ni].w);
    }

    // ---- fused LSTM cell epilogue ----
    const int jbase = blockIdx.x * 32;           // 32 units per block
    const int mbase = blockIdx.y * 128;
    float* Cs = (float*)SM4;                     // [128][33] padded
    float* Hs = Cs + 128 * 33;

    __syncthreads();                             // mainloop smem reads done
    if (!FIRST) {
        #pragma unroll
        for (int k2 = 0; k2 < 4; k2++) {
            int idx = tid + k2 * 256;
            int row = idx >> 3, c4 = (idx & 7) << 2;
            float4 v = *(const float4*)(cmem + (size_t)(mbase + row) * 512 + jbase + c4);
            Cs[row * 33 + c4 + 0] = v.x; Cs[row * 33 + c4 + 1] = v.y;
            Cs[row * 33 + c4 + 2] = v.z; Cs[row * 33 + c4 + 3] = v.w;
        }
    }
    __syncthreads();

    const bool odd = (q & 1);
    #pragma unroll
    for (int ni = 0; ni < 4; ni++) {
        int nloc = wn + ni * 8 + 2 * q;          // n' local; n'%4 = 0 (even q) / 2 (odd q)
        float b0v = bias[blockIdx.x * 128 + nloc];
        float b1v = bias[blockIdx.x * 128 + nloc + 1];
        int jloc = nloc >> 2;
        #pragma unroll
        for (int mi = 0; mi < 4; mi++) {
            float v0 = acc[mi][ni][0] + b0v;     // row m0,   col n'
            float v1 = acc[mi][ni][1] + b1v;     // row m0,   col n'+1
            float v2 = acc[mi][ni][2] + b0v;     // row m0+8, col n'
            float v3 = acc[mi][ni][3] + b1v;     // row m0+8, col n'+1
            // even lane holds (i,f) both rows; odd lane holds (g,o) both rows.
            float s0 = odd ? v0 : v2;
            float s1 = odd ? v1 : v3;
            float rx0 = __shfl_xor_sync(0xffffffffu, s0, 1);
            float rx1 = __shfl_xor_sync(0xffffffffu, s1, 1);
            float gi = odd ? rx0 : v0;
            float gf = odd ? rx1 : v1;
            float gg = odd ? v2 : rx0;
            float go = odd ? v3 : rx1;
            int mloc = wm + mi * 16 + r + (odd ? 8 : 0);
            float ii = fsig(gi), ff = fsig(gf);
            float gv = ftanh(gg), oo = fsig(go);
            float cn = FIRST ? (ii * gv) : fmaf(ff, Cs[mloc * 33 + jloc], ii * gv);
            Cs[mloc * 33 + jloc] = cn;           // in place; unique owner
            Hs[mloc * 33 + jloc] = oo * ftanh(cn);
        }
    }
    __syncthreads();

    // coalesced stores: c, out[b,t,:], permuted+rounded h for next step
    #pragma unroll
    for (int k2 = 0; k2 < 4; k2++) {
        int idx = tid + k2 * 256;
        int row = idx >> 3, c4 = (idx & 7) << 2;
        int gm = mbase + row;
        float4 cv = make_float4(Cs[row * 33 + c4 + 0], Cs[row * 33 + c4 + 1],
                                Cs[row * 33 + c4 + 2], Cs[row * 33 + c4 + 3]);
        *(float4*)(cmem + (size_t)gm * 512 + jbase + c4) = cv;
        float4 hv = make_float4(Hs[row * 33 + c4 + 0], Hs[row * 33 + c4 + 1],
                                Hs[row * 33 + c4 + 2], Hs[row * 33 + c4 + 3]);
        *(float4*)(outp + ((size_t)gm * T + t) * 512 + jbase + c4) = hv;
        float pv[4];
        #pragma unroll
        for (int e = 0; e < 4; e++) {
            int pos = c4 + e;                    // hp[pos] = h[perm16(pos)]
            int src = (pos & ~15) | ((pos & 3) << 2) | ((pos >> 2) & 3);
            pv[e] = tf32f(Hs[row * 33 + src]);
        }
        *(float4*)(hout + (size_t)gm * 512 + jbase + c4) =
            make_float4(pv[0], pv[1], pv[2], pv[3]);
    }
}

// ---------------------------------------------------------------------------
// launch
// ---------------------------------------------------------------------------
extern "C" void kernel_launch(void* const* d_in, const int* in_sizes, int n_in,
                              void* d_out, int out_size)
{
    const float* x   = (const float*)d_in[0];
    const float* W1  = (const float*)d_in[1];
    const float* b1  = (const float*)d_in[2];
    const float* W2  = (const float*)d_in[3];
    const float* b2  = (const float*)d_in[4];
    const float* W3  = (const float*)d_in[5];
    const float* b3  = (const float*)d_in[6];
    const float* Wih = (const float*)d_in[7];
    const float* Whh = (const float*)d_in[8];
    const float* bih = (const float*)d_in[9];
    const float* bhh = (const float*)d_in[10];
    const int*   sl  = (const int*)d_in[11];
    float* out = (float*)d_out;

    const int B = in_sizes[0] / 256;          // 8192
    const int T = out_size / (B * 512);       // 16

    float *W1x_, *b1eff_, *WcombI_, *WihI_, *biascI_, *W2p_, *W3p_, *xp_,
          *h1_, *h2_, *hA_, *hB_, *c_;
    cudaGetSymbolAddress((void**)&W1x_,    g_W1x);
    cudaGetSymbolAddress((void**)&b1eff_,  g_b1eff);
    cudaGetSymbolAddress((void**)&WcombI_, g_WcombI);
    cudaGetSymbolAddress((void**)&WihI_,   g_WihI);
    cudaGetSymbolAddress((void**)&biascI_, g_biascI);
    cudaGetSymbolAddress((void**)&W2p_,    g_W2p);
    cudaGetSymbolAddress((void**)&W3p_,    g_W3p);
    cudaGetSymbolAddress((void**)&xp_,     g_xp);
    cudaGetSymbolAddress((void**)&h1_,     g_h1);
    cudaGetSymbolAddress((void**)&h2_,     g_h2);
    cudaGetSymbolAddress((void**)&hA_,     g_hA);
    cudaGetSymbolAddress((void**)&hB_,     g_hB);
    cudaGetSymbolAddress((void**)&c_,      g_c);

    dim3 blk(256);
    dim3 gMLP(512 / 128, B / 128);    // (4, 64)
    dim3 gGate(2048 / 128, B / 128);  // (16, 64)

    int prep_threads = B * 256;
    prep_kernel<<<(prep_threads + 255) / 256, 256>>>(x, W1, b1, W2, W3,
                                                     Wih, Whh, bih, bhh, sl, B);

    // MLP
    gemm_mlp<1><<<gMLP, blk>>>(xp_, 256, W1x_, 256, b1eff_, h1_, 512, 256);
    gemm_mlp<1><<<gMLP, blk>>>(h1_, 512, W2p_, 512, b2,     h2_, 512, 512);
    gemm_mlp<2><<<gMLP, blk>>>(h2_, 512, W3p_, 512, b3,     hA_, 512, 512); // x0

    // LSTM: fused gates GEMM + cell, h double-buffered
    float* hin = hA_;
    float* hout = hB_;
    for (int t = 0; t < T; ++t) {
        const float* Wg = (t == 0) ? WihI_ : WcombI_;
        if (t == 0)
            gemm_lstm<1><<<gGate, blk>>>(hin, Wg, biascI_, c_, out, hout, t, T);
        else
            gemm_lstm<0><<<gGate, blk>>>(hin, Wg, biascI_, c_, out, hout, t, T);
        float* tmp = hin; hin = hout; hout = tmp;
    }
}

// round 6
// speedup vs baseline: 2.4761x; 1.8265x over previous
#include <cuda_runtime.h>
#include <cuda_fp16.h>
#include <math.h>

// ---------------------------------------------------------------------------
//   x:[B,256]  W1:[512,273] b1:[512]  W2:[512,512] b2  W3:[512,512] b3
//   Wih:[2048,512] Whh:[2048,512] bih:[2048] bhh:[2048]  sentence_len (int)
//   out:[B,T,512] fp32
//
// fp16 mma.sync (m16n8k16, fp32 accumulate) GEMMs. fp16 e5m10 has the same
// 10-bit mantissa as tf32, so precision matches the tf32 version (~4e-4).
// Operands stored as half with pair-permuted K layout so the mainloop is
// pure cp.async + LDS.128 + HMMA. LSTM algebra: inp==h after step 0 ->
// Wcomb = Wih+Whh halves LSTM FLOPs. LSTM cell fused into gates-GEMM
// epilogue via gate-interleaved weights (n' = 4j+gate) + lane^1 shuffle.
// ---------------------------------------------------------------------------

#define MAXB 8192

__device__ __align__(256) __half g_W1x[512 * 256];      // perm half W1[:,17:273]
__device__ __align__(256) float  g_b1eff[512];          // b1 + W1[:, 20-len]
__device__ __align__(256) __half g_WcombI[2048 * 512];  // gate-interleaved perm (Wih+Whh)
__device__ __align__(256) __half g_WihI[2048 * 512];    // gate-interleaved perm Wih (t=0)
__device__ __align__(256) float  g_biascI[2048];        // gate-interleaved bih+bhh
__device__ __align__(256) __half g_W2p[512 * 512];
__device__ __align__(256) __half g_W3p[512 * 512];
__device__ __align__(256) __half g_xp[MAXB * 256];      // perm half x
__device__ __align__(256) __half g_h1[MAXB * 512];
__device__ __align__(256) __half g_h2[MAXB * 512];
__device__ __align__(256) __half g_hA[MAXB * 512];      // perm half h ping
__device__ __align__(256) __half g_hB[MAXB * 512];      // perm half h pong
__device__ __align__(256) float  g_c[MAXB * 512];

// ---------------------------------------------------------------------------
// helpers
// ---------------------------------------------------------------------------
// involutive permutation on 4-bit index: swap the two 2-bit fields.
// Applied to PAIR indices within 16-pair (32-half) blocks: stored pair
// position j holds original pair perm16(j); thread q's uint4 at position
// pair 4q yields pairs {q, q+4, q+8, q+12}.
__device__ __host__ __forceinline__ int perm16(int p) {
    return (p & ~15) | ((p & 3) << 2) | ((p >> 2) & 3);
}
// stored half position -> original k (within a 32-half block structure)
__device__ __forceinline__ int kmap(int pos) {
    return (pos & ~31) | (perm16((pos >> 1) & 15) << 1) | (pos & 1);
}

__device__ __forceinline__ float fsig(float x)  { return 1.f / (1.f + __expf(-x)); }
__device__ __forceinline__ float ftanh(float x) { return 2.f / (1.f + __expf(-2.f * x)) - 1.f; }
__device__ __forceinline__ float sigacc(float x) { return 1.f / (1.f + expf(-x)); }

__device__ __forceinline__ void cpasync16(void* dst, const void* src) {
    unsigned d = (unsigned)__cvta_generic_to_shared(dst);
    asm volatile("cp.async.cg.shared.global [%0], [%1], 16;\n" :: "r"(d), "l"(src));
}

// m16n8k16 fp16 MMA, fp32 accumulate
__device__ __forceinline__ void mma16(float* c,
                                      unsigned a0, unsigned a1, unsigned a2, unsigned a3,
                                      unsigned b0, unsigned b1) {
    asm volatile(
        "mma.sync.aligned.m16n8k16.row.col.f32.f16.f16.f32 "
        "{%0,%1,%2,%3}, {%4,%5,%6,%7}, {%8,%9}, {%0,%1,%2,%3};\n"
        : "+f"(c[0]), "+f"(c[1]), "+f"(c[2]), "+f"(c[3])
        : "r"(a0), "r"(a1), "r"(a2), "r"(a3), "r"(b0), "r"(b1));
}

// ---------------------------------------------------------------------------
// prep: permuted fp16 operand copies, fused biases.
// ---------------------------------------------------------------------------
__global__ void prep_kernel(const float* __restrict__ x,
                            const float* __restrict__ W1, const float* __restrict__ b1,
                            const float* __restrict__ W2, const float* __restrict__ W3,
                            const float* __restrict__ Wih, const float* __restrict__ Whh,
                            const float* __restrict__ bih, const float* __restrict__ bhh,
                            const int* __restrict__ slen, int B)
{
    int i = blockIdx.x * blockDim.x + threadIdx.x;

    if (i < 2048 * 512) {                       // LSTM weights: interleave N, permute K
        int np = i >> 9, p = i & 511;
        int gate = np & 3, j = np >> 2;
        int orig = (gate * 512 + j) * 512 + kmap(p);
        float wv = Wih[orig];
        float wh = Whh[orig];
        g_WihI[i]   = __float2half_rn(wv);
        g_WcombI[i] = __float2half_rn(wv + wh);
    }
    if (i < 512 * 512) {                        // W2, W3 (K-permuted)
        int n = i >> 9, p = i & 511;
        int k = kmap(p);
        g_W2p[i] = __float2half_rn(W2[n * 512 + k]);
        g_W3p[i] = __float2half_rn(W3[n * 512 + k]);
    }
    if (i < 512 * 256) {                        // W1 noise columns
        int n = i >> 8, p = i & 255;
        g_W1x[i] = __float2half_rn(W1[n * 273 + 17 + kmap(p)]);
    }
    if (i < B * 256) {                          // x permuted fp16
        int b = i >> 8, p = i & 255;
        g_xp[i] = __float2half_rn(x[b * 256 + kmap(p)]);
    }
    if (i < 2048) {                             // interleaved fused bias
        int gate = i & 3, j = i >> 2;
        g_biascI[i] = bih[gate * 512 + j] + bhh[gate * 512 + j];
    }
    if (i < 512) {
        int hot = 20 - *slen;
        g_b1eff[i] = b1[i] + W1[i * 273 + hot];
    }
}

// ---------------------------------------------------------------------------
// MLP GEMM: C[M,N] = act( A[M,K] * W[N,K]^T + bias[N] ), half operands,
// pair-permuted K. Block 128x128, BK=32 halves (64B/row), 3-stage cp.async,
// 8 warps (2x4), warp 64x32, mma m16n8k16. ACT: 1=relu, 2=sigmoid.
// Stores permuted half (output always feeds a next GEMM as A).
// ---------------------------------------------------------------------------
template <int ACT>
__global__ __launch_bounds__(256, 2)
void gemm_mlp(const __half* __restrict__ A, int lda,
              const __half* __restrict__ Bm, int ldb,
              const float* __restrict__ bias,
              __half* __restrict__ C, int ldc, int K)
{
    __shared__ uint4 As[3][512];                 // 128 rows x 4 chunks(16B)
    __shared__ uint4 Bs[3][512];

    const int tid  = threadIdx.x;
    const int lane = tid & 31;
    const int warp = tid >> 5;
    const int wm = (warp >> 2) * 64;
    const int wn = (warp & 3) * 32;
    const int r = lane >> 2;
    const int q = lane & 3;

    const __half* Ab = A  + (size_t)blockIdx.y * 128 * lda;
    const __half* Bb = Bm + (size_t)blockIdx.x * 128 * ldb;

    const int lr = tid >> 2;
    const int lc = tid & 3;
    const int KT = K >> 5;                       // 32 halves per tile

    float acc[4][4][4];
    #pragma unroll
    for (int i = 0; i < 4; i++)
        #pragma unroll
        for (int j = 0; j < 4; j++)
            #pragma unroll
            for (int k = 0; k < 4; k++) acc[i][j][k] = 0.f;

    auto ld_stage = [&](int s, int kt) {
        const int k0 = kt << 5;
        int row = lr;
        cpasync16(&As[s][row * 4 + (lc ^ ((row >> 1) & 3))], Ab + (size_t)row * lda + k0 + 8 * lc);
        cpasync16(&Bs[s][row * 4 + (lc ^ ((row >> 1) & 3))], Bb + (size_t)row * ldb + k0 + 8 * lc);
        row = lr + 64;
        cpasync16(&As[s][row * 4 + (lc ^ ((row >> 1) & 3))], Ab + (size_t)row * lda + k0 + 8 * lc);
        cpasync16(&Bs[s][row * 4 + (lc ^ ((row >> 1) & 3))], Bb + (size_t)row * ldb + k0 + 8 * lc);
        asm volatile("cp.async.commit_group;\n" ::);
    };

    ld_stage(0, 0);
    ld_stage(1, 1);

    for (int kt = 0; kt < KT; kt++) {
        const int s = kt % 3;
        if (kt >= KT - 2) asm volatile("cp.async.wait_group 0;\n" ::);
        else              asm volatile("cp.async.wait_group 1;\n" ::);
        __syncthreads();

        const int ktn = kt + 2;
        if (ktn < KT) ld_stage(ktn % 3, ktn);

        // uint4 per row: x=pair q, y=pair q+4, z=pair q+8, w=pair q+12
        uint4 af[4][2], bf[4];
        #pragma unroll
        for (int mi = 0; mi < 4; mi++) {
            int r0 = wm + mi * 16 + r;
            af[mi][0] = As[s][r0 * 4 + (q ^ ((r0 >> 1) & 3))];
            int r1 = r0 + 8;
            af[mi][1] = As[s][r1 * 4 + (q ^ ((r1 >> 1) & 3))];
        }
        #pragma unroll
        for (int ni = 0; ni < 4; ni++) {
            int rb = wn + ni * 8 + r;
            bf[ni] = Bs[s][rb * 4 + (q ^ ((rb >> 1) & 3))];
        }

        // k16 chunk 0 (pairs q, q+4)
        #pragma unroll
        for (int mi = 0; mi < 4; mi++)
            #pragma unroll
            for (int ni = 0; ni < 4; ni++)
                mma16(acc[mi][ni], af[mi][0].x, af[mi][1].x, af[mi][0].y, af[mi][1].y,
                      bf[ni].x, bf[ni].y);
        // k16 chunk 1 (pairs q+8, q+12)
        #pragma unroll
        for (int mi = 0; mi < 4; mi++)
            #pragma unroll
            for (int ni = 0; ni < 4; ni++)
                mma16(acc[mi][ni], af[mi][0].z, af[mi][1].z, af[mi][0].w, af[mi][1].w,
                      bf[ni].z, bf[ni].w);
    }

    #pragma unroll
    for (int mi = 0; mi < 4; mi++) {
        int m0 = blockIdx.y * 128 + wm + mi * 16 + r;
        #pragma unroll
        for (int ni = 0; ni < 4; ni++) {
            int n = blockIdx.x * 128 + wn + ni * 8 + 2 * q;
            float b0v = bias[n], b1v = bias[n + 1];
            float v00 = acc[mi][ni][0] + b0v, v01 = acc[mi][ni][1] + b1v;
            float v10 = acc[mi][ni][2] + b0v, v11 = acc[mi][ni][3] + b1v;
            if (ACT == 1) {
                v00 = fmaxf(v00, 0.f); v01 = fmaxf(v01, 0.f);
                v10 = fmaxf(v10, 0.f); v11 = fmaxf(v11, 0.f);
            } else {
                v00 = sigacc(v00); v01 = sigacc(v01);
                v10 = sigacc(v10); v11 = sigacc(v11);
            }
            // (n, n+1) is one K-pair: store half2 at the permuted pair slot
            int sp = (n & ~31) | (perm16((n >> 1) & 15) << 1);
            *(__half2*)(C + (size_t)m0 * ldc + sp) =
                __floats2half2_rn(v00, v01);
            *(__half2*)(C + (size_t)(m0 + 8) * ldc + sp) =
                __floats2half2_rn(v10, v11);
        }
    }
}

// ---------------------------------------------------------------------------
// Fused gates-GEMM + LSTM cell (same mainloop, fp16 operands).
// ---------------------------------------------------------------------------
template <int FIRST>
__global__ __launch_bounds__(256, 2)
void gemm_lstm(const __half* __restrict__ A,     // hin [B,512] perm half
               const __half* __restrict__ Bm,    // WgI [2048,512]
               const float* __restrict__ bias,   // biascI [2048]
               float* __restrict__ cmem,         // g_c [B,512]
               float* __restrict__ outp,         // out [B,T,512]
               __half* __restrict__ hout,        // next h [B,512] perm half
               int t, int T)
{
    __shared__ uint4 SM4[3072];                  // 48KB: pipeline, then tiles
    uint4* As = SM4;
    uint4* Bs = SM4 + 1536;

    const int tid  = threadIdx.x;
    const int lane = tid & 31;
    const int warp = tid >> 5;
    const int wm = (warp >> 2) * 64;
    const int wn = (warp & 3) * 32;
    const int r = lane >> 2;
    const int q = lane & 3;

    const __half* Ab = A  + (size_t)blockIdx.y * 128 * 512;
    const __half* Bb = Bm + (size_t)blockIdx.x * 128 * 512;

    const int lr = tid >> 2;
    const int lc = tid & 3;
    const int KT = 16;                           // K = 512 halves / 32

    float acc[4][4][4];
    #pragma unroll
    for (int i = 0; i < 4; i++)
        #pragma unroll
        for (int j = 0; j < 4; j++)
            #pragma unroll
            for (int k = 0; k < 4; k++) acc[i][j][k] = 0.f;

    auto ld_stage = [&](int s, int kt) {
        const int k0 = kt << 5;
        int row = lr;
        cpasync16(&As[s * 512 + row * 4 + (lc ^ ((row >> 1) & 3))], Ab + (size_t)row * 512 + k0 + 8 * lc);
        cpasync16(&Bs[s * 512 + row * 4 + (lc ^ ((row >> 1) & 3))], Bb + (size_t)row * 512 + k0 + 8 * lc);
        row = lr + 64;
        cpasync16(&As[s * 512 + row * 4 + (lc ^ ((row >> 1) & 3))], Ab + (size_t)row * 512 + k0 + 8 * lc);
        cpasync16(&Bs[s * 512 + row * 4 + (lc ^ ((row >> 1) & 3))], Bb + (size_t)row * 512 + k0 + 8 * lc);
        asm volatile("cp.async.commit_group;\n" ::);
    };

    ld_stage(0, 0);
    ld_stage(1, 1);

    for (int kt = 0; kt < KT; kt++) {
        const int s = kt % 3;
        if (kt >= KT - 2) asm volatile("cp.async.wait_group 0;\n" ::);
        else              asm volatile("cp.async.wait_group 1;\n" ::);
        __syncthreads();

        const int ktn = kt + 2;
        if (ktn < KT) ld_stage(ktn % 3, ktn);

        uint4 af[4][2], bf[4];
        #pragma unroll
        for (int mi = 0; mi < 4; mi++) {
            int r0 = wm + mi * 16 + r;
            af[mi][0] = As[s * 512 + r0 * 4 + (q ^ ((r0 >> 1) & 3))];
            int r1 = r0 + 8;
            af[mi][1] = As[s * 512 + r1 * 4 + (q ^ ((r1 >> 1) & 3))];
        }
        #pragma unroll
        for (int ni = 0; ni < 4; ni++) {
            int rb = wn + ni * 8 + r;
            bf[ni] = Bs[s * 512 + rb * 4 + (q ^ ((rb >> 1) & 3))];
        }

        #pragma unroll
        for (int mi = 0; mi < 4; mi++)
            #pragma unroll
            for (int ni = 0; ni < 4; ni++)
                mma16(acc[mi][ni], af[mi][0].x, af[mi][1].x, af[mi][0].y, af[mi][1].y,
                      bf[ni].x, bf[ni].y);
        #pragma unroll
        for (int mi = 0; mi < 4; mi++)
            #pragma unroll
            for (int ni = 0; ni < 4; ni++)
                mma16(acc[mi][ni], af[mi][0].z, af[mi][1].z, af[mi][0].w, af[mi][1].w,
                      bf[ni].z, bf[ni].w);
    }

    // ---- fused LSTM cell epilogue ----
    const int jbase = blockIdx.x * 32;           // 32 units per block
    const int mbase = blockIdx.y * 128;
    float* Cs = (float*)SM4;                     // [128][33] padded
    float* Hs = Cs + 128 * 33;

    __syncthreads();
    if (!FIRST) {
        #pragma unroll
        for (int k2 = 0; k2 < 4; k2++) {
            int idx = tid + k2 * 256;
            int row = idx >> 3, c4 = (idx & 7) << 2;
            float4 v = *(const float4*)(cmem + (size_t)(mbase + row) * 512 + jbase + c4);
            Cs[row * 33 + c4 + 0] = v.x; Cs[row * 33 + c4 + 1] = v.y;
            Cs[row * 33 + c4 + 2] = v.z; Cs[row * 33 + c4 + 3] = v.w;
        }
    }
    __syncthreads();

    const bool odd = (q & 1);
    #pragma unroll
    for (int ni = 0; ni < 4; ni++) {
        int nloc = wn + ni * 8 + 2 * q;
        float b0v = bias[blockIdx.x * 128 + nloc];
        float b1v = bias[blockIdx.x * 128 + nloc + 1];
        int jloc = nloc >> 2;
        #pragma unroll
        for (int mi = 0; mi < 4; mi++) {
            float v0 = acc[mi][ni][0] + b0v;
            float v1 = acc[mi][ni][1] + b1v;
            float v2 = acc[mi][ni][2] + b0v;
            float v3 = acc[mi][ni][3] + b1v;
            float s0 = odd ? v0 : v2;
            float s1 = odd ? v1 : v3;
            float rx0 = __shfl_xor_sync(0xffffffffu, s0, 1);
            float rx1 = __shfl_xor_sync(0xffffffffu, s1, 1);
            float gi = odd ? rx0 : v0;
            float gf = odd ? rx1 : v1;
            float gg = odd ? v2 : rx0;
            float go = odd ? v3 : rx1;
            int mloc = wm + mi * 16 + r + (odd ? 8 : 0);
            float ii = fsig(gi), ff = fsig(gf);
            float gv = ftanh(gg), oo = fsig(go);
            float cn = FIRST ? (ii * gv) : fmaf(ff, Cs[mloc * 33 + jloc], ii * gv);
            Cs[mloc * 33 + jloc] = cn;
            Hs[mloc * 33 + jloc] = oo * ftanh(cn);
        }
    }
    __syncthreads();

    // coalesced stores: c, out[b,t,:], permuted fp16 h for next step
    #pragma unroll
    for (int k2 = 0; k2 < 4; k2++) {
        int idx = tid + k2 * 256;
        int row = idx >> 3, c4 = (idx & 7) << 2;
        int gm = mbase + row;
        float4 cv = make_float4(Cs[row * 33 + c4 + 0], Cs[row * 33 + c4 + 1],
                                Cs[row * 33 + c4 + 2], Cs[row * 33 + c4 + 3]);
        *(float4*)(cmem + (size_t)gm * 512 + jbase + c4) = cv;
        float4 hv = make_float4(Hs[row * 33 + c4 + 0], Hs[row * 33 + c4 + 1],
                                Hs[row * 33 + c4 + 2], Hs[row * 33 + c4 + 3]);
        *(float4*)(outp + ((size_t)gm * T + t) * 512 + jbase + c4) = hv;
        // stored pairs j0, j0+1 take source pairs perm16(j0), perm16(j0+1)
        int j0 = c4 >> 1;
        int s0 = perm16(j0) << 1, s1 = perm16(j0 + 1) << 1;
        __half2 h2a = __floats2half2_rn(Hs[row * 33 + s0], Hs[row * 33 + s0 + 1]);
        __half2 h2b = __floats2half2_rn(Hs[row * 33 + s1], Hs[row * 33 + s1 + 1]);
        uint2 pk;
        pk.x = *(unsigned*)&h2a;
        pk.y = *(unsigned*)&h2b;
        *(uint2*)(hout + (size_t)gm * 512 + jbase + c4) = pk;
    }
}

// ---------------------------------------------------------------------------
// launch
// ---------------------------------------------------------------------------
extern "C" void kernel_launch(void* const* d_in, const int* in_sizes, int n_in,
                              void* d_out, int out_size)
{
    const float* x   = (const float*)d_in[0];
    const float* W1  = (const float*)d_in[1];
    const float* b1  = (const float*)d_in[2];
    const float* W2  = (const float*)d_in[3];
    const float* b2  = (const float*)d_in[4];
    const float* W3  = (const float*)d_in[5];
    const float* b3  = (const float*)d_in[6];
    const float* Wih = (const float*)d_in[7];
    const float* Whh = (const float*)d_in[8];
    const float* bih = (const float*)d_in[9];
    const float* bhh = (const float*)d_in[10];
    const int*   sl  = (const int*)d_in[11];
    float* out = (float*)d_out;

    const int B = in_sizes[0] / 256;          // 8192
    const int T = out_size / (B * 512);       // 16

    __half *W1x_, *WcombI_, *WihI_, *W2p_, *W3p_, *xp_, *h1_, *h2_, *hA_, *hB_;
    float *b1eff_, *biascI_, *c_;
    cudaGetSymbolAddress((void**)&W1x_,    g_W1x);
    cudaGetSymbolAddress((void**)&b1eff_,  g_b1eff);
    cudaGetSymbolAddress((void**)&WcombI_, g_WcombI);
    cudaGetSymbolAddress((void**)&WihI_,   g_WihI);
    cudaGetSymbolAddress((void**)&biascI_, g_biascI);
    cudaGetSymbolAddress((void**)&W2p_,    g_W2p);
    cudaGetSymbolAddress((void**)&W3p_,    g_W3p);
    cudaGetSymbolAddress((void**)&xp_,     g_xp);
    cudaGetSymbolAddress((void**)&h1_,     g_h1);
    cudaGetSymbolAddress((void**)&h2_,     g_h2);
    cudaGetSymbolAddress((void**)&hA_,     g_hA);
    cudaGetSymbolAddress((void**)&hB_,     g_hB);
    cudaGetSymbolAddress((void**)&c_,      g_c);

    dim3 blk(256);
    dim3 gMLP(512 / 128, B / 128);    // (4, 64)
    dim3 gGate(2048 / 128, B / 128);  // (16, 64)

    int prep_threads = B * 256;
    prep_kernel<<<(prep_threads + 255) / 256, 256>>>(x, W1, b1, W2, W3,
                                                     Wih, Whh, bih, bhh, sl, B);

    // MLP
    gemm_mlp<1><<<gMLP, blk>>>(xp_, 256, W1x_, 256, b1eff_, h1_, 512, 256);
    gemm_mlp<1><<<gMLP, blk>>>(h1_, 512, W2p_, 512, b2,     h2_, 512, 512);
    gemm_mlp<2><<<gMLP, blk>>>(h2_, 512, W3p_, 512, b3,     hA_, 512, 512); // x0

    // LSTM: fused gates GEMM + cell, h double-buffered
    __half* hin = hA_;
    __half* hout = hB_;
    for (int t = 0; t < T; ++t) {
        const __half* Wg = (t == 0) ? WihI_ : WcombI_;
        if (t == 0)
            gemm_lstm<1><<<gGate, blk>>>(hin, Wg, biascI_, c_, out, hout, t, T);
        else
            gemm_lstm<0><<<gGate, blk>>>(hin, Wg, biascI_, c_, out, hout, t, T);
        __half* tmp = hin; hin = hout; hout = tmp;
    }
}